// round 16
// baseline (speedup 1.0000x reference)
#include <cuda_runtime.h>
#include <cstdint>

#define Bv 8192
#define Mv 512
#define Ov 128
#define NCONC 296   // 148 SMs x 2 CTAs/SM = one wave

// ---- smem byte offsets ----
#define SM_XH   0        // x bf16: 512 rows * 128B (chunk-XOR swizzled) = 65536
#define SM_LN   65536    // lam^T bf16 (o-row-permuted): 128 rows * 128B = 16384
#define SM_SRED 81920    // 32 x 64 f32 partial column sums = 8192
#define SM_POOL 90112    // pooled[128] f32 = 512
#define SMEM_BYTES 90624

__device__ __forceinline__ uint32_t cvta_smem(const void* p) {
    uint32_t a;
    asm("{ .reg .u64 t; cvta.to.shared.u64 t, %1; cvt.u32.u64 %0, t; }" : "=r"(a) : "l"(p));
    return a;
}

__device__ __forceinline__ uint32_t pack_bf16x2(float lo, float hi) {
    uint32_t r;
    asm("cvt.rn.bf16x2.f32 %0, %1, %2;" : "=r"(r) : "f"(hi), "f"(lo));
    return r;
}

__device__ __forceinline__ void ldsm4(uint32_t addr, uint32_t r[4]) {
    asm volatile("ldmatrix.sync.aligned.m8n8.x4.shared.b16 {%0,%1,%2,%3}, [%4];"
        : "=r"(r[0]), "=r"(r[1]), "=r"(r[2]), "=r"(r[3]) : "r"(addr));
}

__device__ __forceinline__ void hmma(float d[4], const uint32_t a[4], const uint32_t b[2]) {
    asm volatile("mma.sync.aligned.m16n8k16.row.col.f32.bf16.bf16.f32 "
        "{%0,%1,%2,%3}, {%4,%5,%6,%7}, {%8,%9}, {%0,%1,%2,%3};"
        : "+f"(d[0]), "+f"(d[1]), "+f"(d[2]), "+f"(d[3])
        : "r"(a[0]), "r"(a[1]), "r"(a[2]), "r"(a[3]), "r"(b[0]), "r"(b[1]));
}

// 256-bit global load (proven form on this toolchain: L2::evict_last + v8.b32)
__device__ __forceinline__ void ldg256(const void* p, uint32_t r[8]) {
    asm volatile("ld.global.L2::evict_last.v8.b32 {%0,%1,%2,%3,%4,%5,%6,%7}, [%8];"
        : "=r"(r[0]), "=r"(r[1]), "=r"(r[2]), "=r"(r[3]),
          "=r"(r[4]), "=r"(r[5]), "=r"(r[6]), "=r"(r[7])
        : "l"(p));
}

__device__ __forceinline__ void stg_cs4(float* p, float a, float b, float c, float d) {
    asm volatile("st.global.cs.v4.f32 [%0], {%1,%2,%3,%4};"
        :: "l"(p), "f"(a), "f"(b), "f"(c), "f"(d) : "memory");
}

extern __shared__ char smem[];

__global__ __launch_bounds__(256, 2)
void eq_mma13_kernel(const float* __restrict__ x,
                     const float* __restrict__ lam,
                     const float* __restrict__ gam,
                     float* __restrict__ out)
{
    const uint32_t sb = cvta_smem(smem);
    const int t = threadIdx.x;
    const int b = blockIdx.x;
    const int w = t >> 5, lane = t & 31, g = lane >> 2, tg = lane & 3;

    // ---- Phase A: x[b] via 256-bit loads -> bf16 smem (swizzled) + sums ----
    {
        const float* xb = x + (size_t)b * (Mv * 64);
        const int f8 = t & 7;             // 32B slot within row (covers 8 f)
        const int tm = t >> 3;            // row phase (0..31)
        float s[8];
        #pragma unroll
        for (int j = 0; j < 8; j++) s[j] = 0.f;
        #pragma unroll 4
        for (int i = 0; i < 16; i++) {
            const int m = tm + 32 * i;
            uint32_t r[8];
            ldg256(xb + m * 64 + 8 * f8, r);
            float v[8];
            #pragma unroll
            for (int j = 0; j < 8; j++) { v[j] = __uint_as_float(r[j]); s[j] += v[j]; }
            uint4 hv;
            hv.x = pack_bf16x2(v[0], v[1]);
            hv.y = pack_bf16x2(v[2], v[3]);
            hv.z = pack_bf16x2(v[4], v[5]);
            hv.w = pack_bf16x2(v[6], v[7]);
            const uint32_t off = (uint32_t)(m * 128 + ((f8 ^ (m & 7)) << 4));
            *(uint4*)(smem + SM_XH + off) = hv;
        }
        *(float4*)(smem + SM_SRED + (tm * 64 + 8 * f8) * 4)
            = make_float4(s[0], s[1], s[2], s[3]);
        *(float4*)(smem + SM_SRED + (tm * 64 + 8 * f8 + 4) * 4)
            = make_float4(s[4], s[5], s[6], s[7]);
    }

    // ---- force next wave's x[b+NCONC] into L2 (reads overlap store phase) ----
    if (b + NCONC < Bv) {
        const char* nx = (const char*)(x + (size_t)(b + NCONC) * (Mv * 64));
        #pragma unroll
        for (int j = 0; j < 4; j++) {
            uint32_t r[8];
            ldg256(nx + (t + 256 * j) * 128, r);
        }
    }

    // ---- Phase B: lam^T -> bf16 smem, o-row-permuted within 16-row groups ----
    {
        const int o = t & 127;
        const int r15 = o & 15;
        const int orow = (o & ~15) | (((r15 & 2) << 2) | ((r15 >> 2) << 1) | (r15 & 1));
        const int q = t >> 7;
        #pragma unroll 4
        for (int j = 0; j < 16; j++) {
            const int fp = q * 16 + j;
            const float v0 = lam[(2 * fp) * Ov + o];
            const float v1 = lam[(2 * fp + 1) * Ov + o];
            const uint32_t h = pack_bf16x2(v0, v1);
            const uint32_t off = (uint32_t)(orow * 128
                + (((fp >> 2) ^ (orow & 7)) << 4) + (fp & 3) * 4);
            *(uint32_t*)(smem + SM_LN + off) = h;
        }
    }
    __syncthreads();

    // ---- finalize s[f] = sum_m x[m,f] ----
    if (t < 64) {
        float v = 0.f;
        #pragma unroll
        for (int r = 0; r < 32; r++)
            v += *(const float*)(smem + SM_SRED + (r * 64 + t) * 4);
        *(float*)(smem + SM_SRED + t * 4) = v;
    }
    __syncthreads();

    // ---- pooled[o] = sum_f s[f] * gam[f,o] (exact fp32) ----
    if (t < 128) {
        float p = 0.f;
        #pragma unroll
        for (int f = 0; f < 64; f++)
            p += *(const float*)(smem + SM_SRED + f * 4) * gam[f * Ov + t];
        *(float*)(smem + SM_POOL + t * 4) = p;
    }
    __syncthreads();

    // ---- Main: per-warp 64 rows x 128 cols, two 32-row sub-passes ----
    const int am = lane & 15, acs = lane >> 4, asw = am & 7;
    const int bo = (lane & 7) | ((lane & 16) >> 1);
    const int bcs = (lane >> 3) & 1, bsw = bo & 7;
    const float* poolp = (const float*)(smem + SM_POOL);
    float* outb = out + (size_t)b * (Mv * Ov);

    #pragma unroll 1
    for (int mp = 0; mp < 2; mp++) {
        const int m0 = w * 64 + mp * 32;
        const uint32_t arow_off = (uint32_t)((m0 + am) * 128);

        uint32_t afr[4][2][4];
        #pragma unroll
        for (int k = 0; k < 4; k++) {
            const uint32_t aadr = sb + SM_XH + arow_off
                                + (uint32_t)((((k << 1) | acs) ^ asw) << 4);
            ldsm4(aadr, afr[k][0]);
            ldsm4(aadr + 16 * 128, afr[k][1]);
        }

        #pragma unroll 1
        for (int nh = 0; nh < 2; nh++) {
            const int o0 = nh * 64;
            float acc[2][8][4];
            #pragma unroll
            for (int i = 0; i < 2; i++)
                #pragma unroll
                for (int j = 0; j < 8; j++)
                    #pragma unroll
                    for (int c = 0; c < 4; c++)
                        acc[i][j][c] = 0.f;

            #pragma unroll
            for (int k = 0; k < 4; k++)
                #pragma unroll
                for (int np = 0; np < 4; np++) {
                    uint32_t bf[4];
                    ldsm4(sb + SM_LN + (uint32_t)((o0 + np * 16 + bo) * 128
                            + ((((k << 1) | bcs) ^ bsw) << 4)), bf);
                    hmma(acc[0][2 * np],     afr[k][0], bf);
                    hmma(acc[0][2 * np + 1], afr[k][0], bf + 2);
                    hmma(acc[1][2 * np],     afr[k][1], bf);
                    hmma(acc[1][2 * np + 1], afr[k][1], bf + 2);
                }

            #pragma unroll
            for (int np = 0; np < 4; np++) {
                const int col = o0 + np * 16 + 4 * tg;
                const float4 pl = *(const float4*)&poolp[col];
                #pragma unroll
                for (int mt = 0; mt < 2; mt++) {
                    const float* a0 = acc[mt][2 * np];
                    const float* a1 = acc[mt][2 * np + 1];
                    float* r0 = outb + (size_t)(m0 + mt * 16 + g) * Ov + col;
                    stg_cs4(r0,
                            fmaxf(a0[0] - pl.x, 0.f), fmaxf(a0[1] - pl.y, 0.f),
                            fmaxf(a1[0] - pl.z, 0.f), fmaxf(a1[1] - pl.w, 0.f));
                    stg_cs4(r0 + 8 * Ov,
                            fmaxf(a0[2] - pl.x, 0.f), fmaxf(a0[3] - pl.y, 0.f),
                            fmaxf(a1[2] - pl.z, 0.f), fmaxf(a1[3] - pl.w, 0.f));
                }
            }
        }
    }
}

extern "C" void kernel_launch(void* const* d_in, const int* in_sizes, int n_in,
                              void* d_out, int out_size)
{
    (void)in_sizes; (void)n_in; (void)out_size;
    const float* x   = (const float*)d_in[0];
    const float* lam = (const float*)d_in[1];
    const float* gam = (const float*)d_in[2];
    float* out = (float*)d_out;

    cudaFuncSetAttribute(eq_mma13_kernel, cudaFuncAttributeMaxDynamicSharedMemorySize,
                         SMEM_BYTES);
    eq_mma13_kernel<<<Bv, 256, SMEM_BYTES>>>(x, lam, gam, out);
}